// round 5
// baseline (speedup 1.0000x reference)
#include <cuda_runtime.h>
#include <cuda_fp16.h>
#include <cstdint>
#include <math.h>

#define NB 8
#define CI 128
#define CO 128
#define HH 64
#define WW 64
#define HW (HH * WW)
#define LT 128
#define NIT 108            // 9 taps * 4 chunks(32ch) * 3 branches
#define NTC 36             // tap*4 + chunk count
#define BROW 136
#define NSTG 3

#define SM_MSM_B  0                       // 27*128*4 = 13824
#define SM_A_B    13824                   // 3 * 8192
#define SM_B_B    (13824 + 3 * 8192)      // 3 * 8704
#define SM_TOTAL  (13824 + 3 * 8192 + 3 * 8704)   // 64512

// Fragment-ready fp16 weights: [it(108)][khalf(2)][t(8)][lane(32)][r(4)][e(2)]
__device__ __align__(16) __half g_Wh[NIT * 4096];

__global__ void repack_kernel(const float* __restrict__ w0,
                              const float* __restrict__ w1,
                              const float* __restrict__ w2) {
  int idx = blockIdx.x * blockDim.x + threadIdx.x;
  if (idx >= NIT * 4096) return;
  int e    = idx & 1;
  int r    = (idx >> 1) & 3;
  int lane = (idx >> 3) & 31;
  int t    = (idx >> 8) & 7;
  int h    = (idx >> 11) & 1;
  int step = idx >> 12;
  int b  = step % 3;
  int tc = step / 3;
  int ch = tc & 3, tap = tc >> 2;
  int o = t * 16 + (lane >> 2) + 8 * (r & 1);
  int k = 2 * (lane & 3) + 8 * (r >> 1) + e;
  int c = ch * 32 + h * 16 + k;
  const float* w = (b == 0) ? w0 : ((b == 1) ? w1 : w2);
  g_Wh[idx] = __float2half_rn(w[(o * CI + c) * 9 + tap]);
}

__device__ __forceinline__ void mma16816(float* c, const uint32_t* a,
                                         const uint32_t* b) {
  asm volatile(
      "mma.sync.aligned.m16n8k16.row.col.f32.f16.f16.f32 "
      "{%0,%1,%2,%3}, {%4,%5,%6,%7}, {%8,%9}, {%0,%1,%2,%3};"
      : "+f"(c[0]), "+f"(c[1]), "+f"(c[2]), "+f"(c[3])
      : "r"(a[0]), "r"(a[1]), "r"(a[2]), "r"(a[3]), "r"(b[0]), "r"(b[1]));
}

__global__ __launch_bounds__(256, 2) void conv25d_mma(
    const float* __restrict__ x, const float* __restrict__ depth,
    const float* __restrict__ fx, float* __restrict__ out) {
  extern __shared__ __align__(16) char smem[];
  float* Msm = (float*)(smem + SM_MSM_B);
  char*  Ab  = smem + SM_A_B;
  char*  Bb  = smem + SM_B_B;

  const int tid = threadIdx.x;
  const int n   = blockIdx.y;
  const int l0  = blockIdx.x * LT;
  const int h0  = l0 >> 6;
  const float* xn = x + (size_t)n * CI * HW;
  const float* dn = depth + (size_t)n * HW;

  // ---- mask precompute (verified) ----
  if (tid < LT) {
    int l = tid, h = h0 + (l >> 6), w = l & 63;
    float d[9];
#pragma unroll
    for (int kh = 0; kh < 3; ++kh)
#pragma unroll
      for (int kw = 0; kw < 3; ++kw) {
        int hh2 = h + kh - 1, ww2 = w + kw - 1;
        bool ok = (((unsigned)hh2) < HH) && (((unsigned)ww2) < WW);
        d[kh * 3 + kw] = ok ? dn[hh2 * WW + ww2] : 0.f;
      }
    float fxn = fx[n];
    float cvalid = (d[4] != 0.f) ? 1.f : 0.f;
    float center = d[4] * cvalid;
    float grid = center / fxn;
    float half = 0.5f * grid;
#pragma unroll
    for (int k = 0; k < 9; ++k) {
      float vld = (d[k] != 0.f) ? cvalid : 0.f;
      float dm = d[k] * vld;
      float m0 = (fabsf(dm - (center + grid)) <= half) ? 1.f : 0.f;
      float m1 = (fabsf(dm - center) <= half) ? 1.f : 0.f;
      m1 = fminf(m1 + 1.f - vld, 1.f);
      float m2 = (fabsf(dm - (center - grid)) <= half) ? 1.f : 0.f;
      Msm[(k * 3 + 0) * LT + l] = m0;
      Msm[(k * 3 + 1) * LT + l] = m1;
      Msm[(k * 3 + 2) * LT + l] = m2;
    }
  }
  __syncthreads();

  const int pc2 = tid >> 5;
  const int pl  = (tid & 31) << 2;
  const int ph  = h0 + (pl >> 6);
  const int pw  = pl & 63;

  const int lane = tid & 31;
  const int wq = tid >> 5;
  const int oq = wq >> 2, lq = wq & 3;
  const int g = lane >> 2, tig = lane & 3;

  float acc[4][4][4];
#pragma unroll
  for (int i = 0; i < 4; ++i)
#pragma unroll
    for (int j = 0; j < 4; ++j)
#pragma unroll
      for (int r = 0; r < 4; ++r) acc[i][j][r] = 0.f;

  // packed x (half2 over channel pair), double-buffered by chunk parity
  uint32_t xr[2][8];

  auto xload = [&](int tc) {
    int ch = tc & 3, tap = tc >> 2;
    int dy = tap / 3 - 1, dx = tap % 3 - 1;
    int hh = ph + dy;
    bool okh = ((unsigned)hh) < HH;
    const float* base = xn + hh * WW + pw + dx;
    int buf = tc & 1;
#pragma unroll
    for (int h = 0; h < 2; ++h) {
      const float* xp = base + (size_t)(ch * 32 + h * 16 + 2 * pc2) * HW;
#pragma unroll
      for (int j = 0; j < 4; ++j) {
        bool ok = okh && (((unsigned)(pw + dx + j)) < WW);
        float f0 = ok ? __ldg(xp + j) : 0.f;
        float f1 = ok ? __ldg(xp + HW + j) : 0.f;
        __half2 p = __floats2half2_rn(f0, f1);
        xr[buf][h * 4 + j] = *(uint32_t*)&p;
      }
    }
  };

  auto bstore = [&](int it) {
    int b = it % 3;
    int tc = it / 3;
    int s = (tc >> 2) * 3 + b;
    int stg = it % NSTG;
    int buf = tc & 1;
    float4 m = *(const float4*)&Msm[s * LT + pl];
    uint32_t keep[4] = {m.x != 0.f ? 0xFFFFFFFFu : 0u, m.y != 0.f ? 0xFFFFFFFFu : 0u,
                        m.z != 0.f ? 0xFFFFFFFFu : 0u, m.w != 0.f ? 0xFFFFFFFFu : 0u};
    uint32_t* bp = (uint32_t*)(Bb + stg * 8704);
#pragma unroll
    for (int h = 0; h < 2; ++h) {
      *(uint4*)&bp[(h * 8 + pc2) * BROW + pl] =
          make_uint4(xr[buf][h * 4 + 0] & keep[0], xr[buf][h * 4 + 1] & keep[1],
                     xr[buf][h * 4 + 2] & keep[2], xr[buf][h * 4 + 3] & keep[3]);
    }
  };

  auto acp = [&](int it) {
    int stg = it % NSTG;
    uint32_t dsta = (uint32_t)__cvta_generic_to_shared(Ab + stg * 8192 + tid * 16);
    const char* srca = (const char*)g_Wh + (size_t)it * 8192 + tid * 16;
    asm volatile("cp.async.cg.shared.global [%0], [%1], 16;" ::"r"(dsta), "l"(srca));
    asm volatile("cp.async.cg.shared.global [%0], [%1], 16;" ::"r"(dsta + 4096),
                 "l"(srca + 4096));
    asm volatile("cp.async.commit_group;");
  };

  auto mma_step = [&](int stg) {
    const uint4* ap = (const uint4*)(Ab + stg * 8192);
    const uint32_t* bp = (const uint32_t*)(Bb + stg * 8704);
#pragma unroll
    for (int h = 0; h < 2; ++h) {
      uint32_t a[4][4];
#pragma unroll
      for (int i = 0; i < 4; ++i) {
        uint4 q = ap[h * 256 + (oq * 4 + i) * 32 + lane];
        a[i][0] = q.x; a[i][1] = q.y; a[i][2] = q.z; a[i][3] = q.w;
      }
      uint32_t bb[4][2];
#pragma unroll
      for (int j = 0; j < 4; ++j) {
        int lcol = lq * 32 + j * 8 + g;
        bb[j][0] = bp[(h * 8 + tig) * BROW + lcol];
        bb[j][1] = bp[(h * 8 + tig + 4) * BROW + lcol];
      }
#pragma unroll
      for (int i = 0; i < 4; ++i)
#pragma unroll
        for (int j = 0; j < 4; ++j) mma16816(acc[i][j], a[i], bb[j]);
    }
  };

  // prologue: stage 0 B + A groups G0,G1
  xload(0);
  bstore(0);
  acp(0);
  acp(1);

#pragma unroll 1
  for (int it = 0; it < NIT; ++it) {
    asm volatile("cp.async.wait_group 1;");
    __syncthreads();
    if ((it % 3) == 0 && (it / 3 + 1) < NTC) xload(it / 3 + 1);
    if (it + 2 < NIT) acp(it + 2);
    if (it + 1 < NIT) bstore(it + 1);
    mma_step(it % NSTG);
  }

  // ---- epilogue ----
  float* on = out + (size_t)n * CO * HW;
#pragma unroll
  for (int i = 0; i < 4; ++i) {
    int obase = oq * 64 + i * 16 + g;
#pragma unroll
    for (int j = 0; j < 4; ++j) {
      int lcol = l0 + lq * 32 + j * 8 + 2 * tig;
      float2 v0 = make_float2(acc[i][j][0], acc[i][j][1]);
      float2 v1 = make_float2(acc[i][j][2], acc[i][j][3]);
      *(float2*)&on[(size_t)obase * HW + lcol] = v0;
      *(float2*)&on[(size_t)(obase + 8) * HW + lcol] = v1;
    }
  }
}

extern "C" void kernel_launch(void* const* d_in, const int* in_sizes, int n_in,
                              void* d_out, int out_size) {
  const float* x     = (const float*)d_in[0];
  const float* depth = (const float*)d_in[1];
  const float* fx    = (const float*)d_in[2];
  const float* w0    = (const float*)d_in[3];
  const float* w1    = (const float*)d_in[4];
  const float* w2    = (const float*)d_in[5];
  float* out = (float*)d_out;

  cudaFuncSetAttribute(conv25d_mma,
                       cudaFuncAttributeMaxDynamicSharedMemorySize, SM_TOTAL);

  repack_kernel<<<(NIT * 4096 + 255) / 256, 256>>>(w0, w1, w2);
  dim3 grid((HH * WW) / LT, NB);
  conv25d_mma<<<grid, 256, SM_TOTAL>>>(x, depth, fx, out);
}

// round 6
// speedup vs baseline: 1.2752x; 1.2752x over previous
#include <cuda_runtime.h>
#include <cuda_fp16.h>
#include <cstdint>
#include <math.h>

#define NB 8
#define CI 128
#define CO 128
#define HH 64
#define WW 64
#define HW (HH * WW)
#define LT 128
#define NIT 108            // 9 taps * 4 chunks(32ch) * 3 branches
#define NTC 36
#define BROW 136
#define NSTG 3
#define NTHR 128

#define SM_MSM_B  0                       // 27*128*4 = 13824 (packed half2 masks)
#define SM_A_B    13824                   // 3 * 8192
#define SM_B_B    (13824 + 3 * 8192)      // 3 * 8704
#define SM_TOTAL  (13824 + 3 * 8192 + 3 * 8704)   // 64512

// Fragment-ready fp16 weights: [it(108)][khalf(2)][t(8)][lane(32)][r(4)][e(2)]
__device__ __align__(16) __half g_Wh[NIT * 4096];

__global__ void repack_kernel(const float* __restrict__ w0,
                              const float* __restrict__ w1,
                              const float* __restrict__ w2) {
  int idx = blockIdx.x * blockDim.x + threadIdx.x;
  if (idx >= NIT * 4096) return;
  int e    = idx & 1;
  int r    = (idx >> 1) & 3;
  int lane = (idx >> 3) & 31;
  int t    = (idx >> 8) & 7;
  int h    = (idx >> 11) & 1;
  int step = idx >> 12;
  int b  = step % 3;
  int tc = step / 3;
  int ch = tc & 3, tap = tc >> 2;
  int o = t * 16 + (lane >> 2) + 8 * (r & 1);
  int k = 2 * (lane & 3) + 8 * (r >> 1) + e;
  int c = ch * 32 + h * 16 + k;
  const float* w = (b == 0) ? w0 : ((b == 1) ? w1 : w2);
  g_Wh[idx] = __float2half_rn(w[(o * CI + c) * 9 + tap]);
}

__device__ __forceinline__ void mma16816(float* c, const uint32_t* a,
                                         const uint32_t* b) {
  asm volatile(
      "mma.sync.aligned.m16n8k16.row.col.f32.f16.f16.f32 "
      "{%0,%1,%2,%3}, {%4,%5,%6,%7}, {%8,%9}, {%0,%1,%2,%3};"
      : "+f"(c[0]), "+f"(c[1]), "+f"(c[2]), "+f"(c[3])
      : "r"(a[0]), "r"(a[1]), "r"(a[2]), "r"(a[3]), "r"(b[0]), "r"(b[1]));
}
__device__ __forceinline__ uint32_t hmul2u(uint32_t a, uint32_t b) {
  __half2 r = __hmul2(*(__half2*)&a, *(__half2*)&b);
  return *(uint32_t*)&r;
}

__global__ __launch_bounds__(NTHR) void conv25d_mma(
    const float* __restrict__ x, const float* __restrict__ depth,
    const float* __restrict__ fx, float* __restrict__ out) {
  extern __shared__ __align__(16) char smem[];
  uint32_t* Msm = (uint32_t*)(smem + SM_MSM_B);   // [27][LT] half2(m,m)
  char*  Ab  = smem + SM_A_B;
  char*  Bb  = smem + SM_B_B;

  const int tid = threadIdx.x;
  const int n   = blockIdx.y;
  const int l0  = blockIdx.x * LT;
  const int h0  = l0 >> 6;
  const float* xn = x + (size_t)n * CI * HW;
  const float* dn = depth + (size_t)n * HW;

  // ---- mask precompute (verified math), packed half2 ----
  {
    int l = tid, h = h0 + (l >> 6), w = l & 63;
    float d[9];
#pragma unroll
    for (int kh = 0; kh < 3; ++kh)
#pragma unroll
      for (int kw = 0; kw < 3; ++kw) {
        int hh2 = h + kh - 1, ww2 = w + kw - 1;
        bool ok = (((unsigned)hh2) < HH) && (((unsigned)ww2) < WW);
        d[kh * 3 + kw] = ok ? dn[hh2 * WW + ww2] : 0.f;
      }
    float fxn = fx[n];
    float cvalid = (d[4] != 0.f) ? 1.f : 0.f;
    float center = d[4] * cvalid;
    float grid = center / fxn;
    float half = 0.5f * grid;
#pragma unroll
    for (int k = 0; k < 9; ++k) {
      float vld = (d[k] != 0.f) ? cvalid : 0.f;
      float dm = d[k] * vld;
      float m0 = (fabsf(dm - (center + grid)) <= half) ? 1.f : 0.f;
      float m1 = (fabsf(dm - center) <= half) ? 1.f : 0.f;
      m1 = fminf(m1 + 1.f - vld, 1.f);
      float m2 = (fabsf(dm - (center - grid)) <= half) ? 1.f : 0.f;
      __half2 p0 = __float2half2_rn(m0), p1 = __float2half2_rn(m1),
              p2 = __float2half2_rn(m2);
      Msm[(k * 3 + 0) * LT + l] = *(uint32_t*)&p0;
      Msm[(k * 3 + 1) * LT + l] = *(uint32_t*)&p1;
      Msm[(k * 3 + 2) * LT + l] = *(uint32_t*)&p2;
    }
  }
  __syncthreads();

  // producer mapping: cpq = channel-pair quad, l4 = 4 consecutive l
  const int cpq = tid >> 5;            // 0..3
  const int l4  = (tid & 31) << 2;     // 0..124
  const int ph  = h0 + (l4 >> 6);
  const int pw  = l4 & 63;

  // consumer mapping: 4 warps -> 64o x 64l tiles
  const int lane = tid & 31;
  const int wq = tid >> 5;
  const int oq = wq >> 1, lq = wq & 1;
  const int g = lane >> 2, tig = lane & 3;

  float acc[4][8][4];
#pragma unroll
  for (int i = 0; i < 4; ++i)
#pragma unroll
    for (int j = 0; j < 8; ++j)
#pragma unroll
      for (int r = 0; r < 4; ++r) acc[i][j][r] = 0.f;

  uint32_t xr0[16], xr1[16];   // static double buffer (half2-packed x)

  auto xload = [&](int tc, uint32_t* xr) {
    int ch = tc & 3, tap = tc >> 2;
    int dy = tap / 3 - 1, dx = tap % 3 - 1;
    int hh = ph + dy;
    bool okh = ((unsigned)hh) < HH;
    const float* base = xn + hh * WW + pw + dx;
#pragma unroll
    for (int r4 = 0; r4 < 4; ++r4) {
      int c0 = ch * 32 + 2 * cpq + (r4 & 1) * 8 + (r4 >> 1) * 16;
      const float* xp = base + (size_t)c0 * HW;
#pragma unroll
      for (int j = 0; j < 4; ++j) {
        bool ok = okh && (((unsigned)(pw + dx + j)) < WW);
        float f0 = ok ? __ldg(xp + j) : 0.f;
        float f1 = ok ? __ldg(xp + HW + j) : 0.f;
        __half2 p = __floats2half2_rn(f0, f1);
        xr[r4 * 4 + j] = *(uint32_t*)&p;
      }
    }
  };

  auto bstore = [&](int it, int b, int stg, const uint32_t* xr) {
    int tap = (it / 3) >> 2;
    int s = tap * 3 + b;
    uint4 mm = *(const uint4*)&Msm[s * LT + l4];
    uint32_t m[4] = {mm.x, mm.y, mm.z, mm.w};
    uint32_t* bp = (uint32_t*)(Bb + stg * 8704);
#pragma unroll
    for (int r4 = 0; r4 < 4; ++r4) {
      int row = (r4 >> 1) * 8 + (r4 & 1) * 4 + cpq;
      *(uint4*)&bp[row * BROW + l4] =
          make_uint4(hmul2u(xr[r4 * 4 + 0], m[0]), hmul2u(xr[r4 * 4 + 1], m[1]),
                     hmul2u(xr[r4 * 4 + 2], m[2]), hmul2u(xr[r4 * 4 + 3], m[3]));
    }
  };

  auto acp = [&](int it, int stg) {
    uint32_t dsta = (uint32_t)__cvta_generic_to_shared(Ab + stg * 8192 + tid * 16);
    const char* srca = (const char*)g_Wh + (size_t)it * 8192 + tid * 16;
#pragma unroll
    for (int q = 0; q < 4; ++q)
      asm volatile("cp.async.cg.shared.global [%0], [%1], 16;" ::"r"(
                       dsta + q * 2048),
                   "l"(srca + q * 2048));
    asm volatile("cp.async.commit_group;");
  };

  auto mma_step = [&](int stg) {
    const uint4* ap = (const uint4*)(Ab + stg * 8192);
    const uint32_t* bp = (const uint32_t*)(Bb + stg * 8704);
#pragma unroll
    for (int h = 0; h < 2; ++h) {
      uint32_t a[4][4];
#pragma unroll
      for (int i = 0; i < 4; ++i) {
        uint4 q = ap[h * 256 + (oq * 4 + i) * 32 + lane];
        a[i][0] = q.x; a[i][1] = q.y; a[i][2] = q.z; a[i][3] = q.w;
      }
#pragma unroll
      for (int j = 0; j < 8; ++j) {
        uint32_t bb[2];
        int lcol = lq * 64 + j * 8 + g;
        bb[0] = bp[(h * 8 + tig) * BROW + lcol];
        bb[1] = bp[(h * 8 + tig + 4) * BROW + lcol];
#pragma unroll
        for (int i = 0; i < 4; ++i) mma16816(acc[i][j], a[i], bb);
      }
    }
  };

  // prologue
  xload(0, xr0);
  bstore(0, 0, 0, xr0);
  acp(0, 0);
  acp(1, 1);

  // 18 groups x 6 iterations: stage = u%3, chunk parity = (u>=2&&u<=4)
#pragma unroll 1
  for (int tc2 = 0; tc2 < 18; ++tc2) {
    int itb = tc2 * 6;
    int c2 = tc2 * 2;
#pragma unroll
    for (int u = 0; u < 6; ++u) {
      int it = itb + u;
      asm volatile("cp.async.wait_group 1;");
      __syncthreads();
      mma_step(u % 3);
      if (u == 0 && c2 + 1 < NTC) xload(c2 + 1, xr1);
      if (u == 3 && c2 + 2 < NTC) xload(c2 + 2, xr0);
      if (it + 2 < NIT) acp(it + 2, (u + 2) % 3);
      if (it + 1 < NIT) {
        const int bb_ = (u + 1) % 3;                 // branch of it+1
        if (u >= 2 && u <= 4) bstore(it + 1, bb_, (u + 1) % 3, xr1);
        else                  bstore(it + 1, bb_, (u + 1) % 3, xr0);
      }
    }
  }

  // ---- epilogue ----
  float* on = out + (size_t)n * CO * HW;
#pragma unroll
  for (int i = 0; i < 4; ++i) {
    int obase = oq * 64 + i * 16 + g;
#pragma unroll
    for (int j = 0; j < 8; ++j) {
      int lcol = l0 + lq * 64 + j * 8 + 2 * tig;
      float2 v0 = make_float2(acc[i][j][0], acc[i][j][1]);
      float2 v1 = make_float2(acc[i][j][2], acc[i][j][3]);
      *(float2*)&on[(size_t)obase * HW + lcol] = v0;
      *(float2*)&on[(size_t)(obase + 8) * HW + lcol] = v1;
    }
  }
}

extern "C" void kernel_launch(void* const* d_in, const int* in_sizes, int n_in,
                              void* d_out, int out_size) {
  const float* x     = (const float*)d_in[0];
  const float* depth = (const float*)d_in[1];
  const float* fx    = (const float*)d_in[2];
  const float* w0    = (const float*)d_in[3];
  const float* w1    = (const float*)d_in[4];
  const float* w2    = (const float*)d_in[5];
  float* out = (float*)d_out;

  cudaFuncSetAttribute(conv25d_mma,
                       cudaFuncAttributeMaxDynamicSharedMemorySize, SM_TOTAL);

  repack_kernel<<<(NIT * 4096 + 255) / 256, 256>>>(w0, w1, w2);
  dim3 grid((HH * WW) / LT, NB);
  conv25d_mma<<<grid, NTHR, SM_TOTAL>>>(x, depth, fx, out);
}

// round 7
// speedup vs baseline: 1.2784x; 1.0025x over previous
#include <cuda_runtime.h>
#include <cuda_fp16.h>
#include <cstdint>
#include <math.h>

#define NB 8
#define CI 128
#define CO 128
#define HH 64
#define WW 64
#define HW (HH * WW)
#define LT 128
#define NIT 108            // 9 taps * 4 chunks(32ch) * 3 branches
#define NTC 36             // 9 taps * 4 chunks
#define NTHR 128

// Fragment-ready fp16 weights: [it(108)][khalf(2)][t(8)][lane(32)][r(4)][e(2)]
__device__ __align__(16) __half g_Wh[NIT * 4096];

__global__ void repack_kernel(const float* __restrict__ w0,
                              const float* __restrict__ w1,
                              const float* __restrict__ w2) {
  int idx = blockIdx.x * blockDim.x + threadIdx.x;
  if (idx >= NIT * 4096) return;
  int e    = idx & 1;
  int r    = (idx >> 1) & 3;
  int lane = (idx >> 3) & 31;
  int t    = (idx >> 8) & 7;
  int h    = (idx >> 11) & 1;
  int step = idx >> 12;
  int b  = step % 3;
  int tc = step / 3;
  int ch = tc & 3, tap = tc >> 2;
  int o = t * 16 + (lane >> 2) + 8 * (r & 1);
  int k = 2 * (lane & 3) + 8 * (r >> 1) + e;
  int c = ch * 32 + h * 16 + k;
  const float* w = (b == 0) ? w0 : ((b == 1) ? w1 : w2);
  g_Wh[idx] = __float2half_rn(w[(o * CI + c) * 9 + tap]);
}

__device__ __forceinline__ void mma16816(float* c, const uint32_t* a,
                                         const uint32_t* b) {
  asm volatile(
      "mma.sync.aligned.m16n8k16.row.col.f32.f16.f16.f32 "
      "{%0,%1,%2,%3}, {%4,%5,%6,%7}, {%8,%9}, {%0,%1,%2,%3};"
      : "+f"(c[0]), "+f"(c[1]), "+f"(c[2]), "+f"(c[3])
      : "r"(a[0]), "r"(a[1]), "r"(a[2]), "r"(a[3]), "r"(b[0]), "r"(b[1]));
}
__device__ __forceinline__ uint32_t hmul2u(uint32_t a, uint32_t b) {
  __half2 r = __hmul2(*(__half2*)&a, *(__half2*)&b);
  return *(uint32_t*)&r;
}

__global__ __launch_bounds__(NTHR) void conv25d_mma(
    const float* __restrict__ x, const float* __restrict__ depth,
    const float* __restrict__ fx, float* __restrict__ out) {
  __shared__ uint32_t Msm[27 * LT];   // half2(m,m)

  const int tid = threadIdx.x;
  const int n   = blockIdx.y;
  const int l0  = blockIdx.x * LT;
  const int h0  = l0 >> 6;
  const float* xn = x + (size_t)n * CI * HW;
  const float* dn = depth + (size_t)n * HW;

  // ---- mask precompute (verified math), packed half2 ----
  {
    int l = tid, h = h0 + (l >> 6), w = l & 63;
    float d[9];
#pragma unroll
    for (int kh = 0; kh < 3; ++kh)
#pragma unroll
      for (int kw = 0; kw < 3; ++kw) {
        int hh2 = h + kh - 1, ww2 = w + kw - 1;
        bool ok = (((unsigned)hh2) < HH) && (((unsigned)ww2) < WW);
        d[kh * 3 + kw] = ok ? dn[hh2 * WW + ww2] : 0.f;
      }
    float fxn = fx[n];
    float cvalid = (d[4] != 0.f) ? 1.f : 0.f;
    float center = d[4] * cvalid;
    float grid = center / fxn;
    float half = 0.5f * grid;
#pragma unroll
    for (int k = 0; k < 9; ++k) {
      float vld = (d[k] != 0.f) ? cvalid : 0.f;
      float dm = d[k] * vld;
      float m0 = (fabsf(dm - (center + grid)) <= half) ? 1.f : 0.f;
      float m1 = (fabsf(dm - center) <= half) ? 1.f : 0.f;
      m1 = fminf(m1 + 1.f - vld, 1.f);
      float m2 = (fabsf(dm - (center - grid)) <= half) ? 1.f : 0.f;
      __half2 p0 = __float2half2_rn(m0), p1 = __float2half2_rn(m1),
              p2 = __float2half2_rn(m2);
      Msm[(k * 3 + 0) * LT + l] = *(uint32_t*)&p0;
      Msm[(k * 3 + 1) * LT + l] = *(uint32_t*)&p1;
      Msm[(k * 3 + 2) * LT + l] = *(uint32_t*)&p2;
    }
  }
  __syncthreads();   // only barrier in the kernel

  const int lane = tid & 31;
  const int wq = tid >> 5;
  const int oq = wq >> 1, lq = wq & 1;      // warp tile: 64o x 64l
  const int g = lane >> 2, tig = lane & 3;

  float acc[4][8][4];
#pragma unroll
  for (int i = 0; i < 4; ++i)
#pragma unroll
    for (int j = 0; j < 8; ++j)
#pragma unroll
      for (int r = 0; r < 4; ++r) acc[i][j][r] = 0.f;

  // B operand in registers: xv[p*8+j], p = h*2 + q -> channels (c0, c0+1)
  uint32_t xv[32];

  const uint4* wfrag = (const uint4*)g_Wh;

#pragma unroll 1
  for (int tc = 0; tc < NTC; ++tc) {
    int tap = tc >> 2, ch = tc & 3;
    int dy = tap / 3 - 1, dx = tap % 3 - 1;
    int hrow = h0 + lq + dy;
    bool okh = ((unsigned)hrow) < HH;
    const float* rb = xn + hrow * WW;

    // ---- load x fragment (64 scalar LDG, sector-perfect) ----
#pragma unroll
    for (int p = 0; p < 4; ++p) {
      int c0 = ch * 32 + (p >> 1) * 16 + (p & 1) * 8 + 2 * tig;
      const float* xp = rb + (size_t)c0 * HW;
#pragma unroll
      for (int j = 0; j < 8; ++j) {
        int w = j * 8 + g + dx;
        bool ok = okh && (((unsigned)w) < WW);
        float f0 = ok ? __ldg(xp + w) : 0.f;
        float f1 = ok ? __ldg(xp + HW + w) : 0.f;
        __half2 pk = __floats2half2_rn(f0, f1);
        xv[p * 8 + j] = *(uint32_t*)&pk;
      }
    }

    // ---- 3 branches reuse xv ----
#pragma unroll
    for (int b = 0; b < 3; ++b) {
      int it = tc * 3 + b;
      int s = tap * 3 + b;
      uint32_t msk[8];
#pragma unroll
      for (int j = 0; j < 8; ++j)
        msk[j] = Msm[s * LT + lq * 64 + j * 8 + g];

      // A fragments straight from L2-resident packed weights
      uint32_t a[2][4][4];
#pragma unroll
      for (int h = 0; h < 2; ++h)
#pragma unroll
        for (int i = 0; i < 4; ++i) {
          uint4 q = __ldg(&wfrag[(size_t)it * 512 + (h * 8 + oq * 4 + i) * 32 + lane]);
          a[h][i][0] = q.x; a[h][i][1] = q.y; a[h][i][2] = q.z; a[h][i][3] = q.w;
        }

#pragma unroll
      for (int h = 0; h < 2; ++h)
#pragma unroll
        for (int j = 0; j < 8; ++j) {
          uint32_t bb[2];
          bb[0] = hmul2u(xv[(h * 2 + 0) * 8 + j], msk[j]);
          bb[1] = hmul2u(xv[(h * 2 + 1) * 8 + j], msk[j]);
#pragma unroll
          for (int i = 0; i < 4; ++i) mma16816(acc[i][j], a[h][i], bb);
        }

      // warm next chunk's x lines into L1 during the middle branch
      if (b == 1 && tc + 1 < NTC) {
        int tcn = tc + 1, chn = tcn & 3, tapn = tcn >> 2;
        int dyn_ = tapn / 3 - 1;
        int hr = h0 + lq + dyn_;
        if (((unsigned)hr) < HH) {
          const float* pa = xn + (size_t)(chn * 32 + lane) * HW + hr * WW;
          asm volatile("prefetch.global.L1 [%0];" ::"l"(pa));
          asm volatile("prefetch.global.L1 [%0];" ::"l"(pa + 32));
        }
      }
    }
  }

  // ---- epilogue (unchanged mapping) ----
  float* on = out + (size_t)n * CO * HW;
#pragma unroll
  for (int i = 0; i < 4; ++i) {
    int obase = oq * 64 + i * 16 + g;
#pragma unroll
    for (int j = 0; j < 8; ++j) {
      int lcol = l0 + lq * 64 + j * 8 + 2 * tig;
      float2 v0 = make_float2(acc[i][j][0], acc[i][j][1]);
      float2 v1 = make_float2(acc[i][j][2], acc[i][j][3]);
      *(float2*)&on[(size_t)obase * HW + lcol] = v0;
      *(float2*)&on[(size_t)(obase + 8) * HW + lcol] = v1;
    }
  }
}

extern "C" void kernel_launch(void* const* d_in, const int* in_sizes, int n_in,
                              void* d_out, int out_size) {
  const float* x     = (const float*)d_in[0];
  const float* depth = (const float*)d_in[1];
  const float* fx    = (const float*)d_in[2];
  const float* w0    = (const float*)d_in[3];
  const float* w1    = (const float*)d_in[4];
  const float* w2    = (const float*)d_in[5];
  float* out = (float*)d_out;

  repack_kernel<<<(NIT * 4096 + 255) / 256, 256>>>(w0, w1, w2);
  dim3 grid((HH * WW) / LT, NB);
  conv25d_mma<<<grid, NTHR>>>(x, depth, fx, out);
}

// round 8
// speedup vs baseline: 1.2828x; 1.0034x over previous
#include <cuda_runtime.h>
#include <cuda_fp16.h>
#include <cstdint>
#include <math.h>

#define NB 8
#define CI 128
#define CO 128
#define HH 64
#define WW 64
#define HW (HH * WW)
#define LT 128
#define NIT 108            // 9 taps * 4 chunks(32ch) * 3 branches
#define NTC 36             // 9 taps * 4 chunks
#define NTHR 256

// Fragment-ready fp16 weights: [it(108)][khalf(2)][t(8)][lane(32)][r(4)][e(2)]
__device__ __align__(16) __half g_Wh[NIT * 4096];

__global__ void repack_kernel(const float* __restrict__ w0,
                              const float* __restrict__ w1,
                              const float* __restrict__ w2) {
  int idx = blockIdx.x * blockDim.x + threadIdx.x;
  if (idx >= NIT * 4096) return;
  int e    = idx & 1;
  int r    = (idx >> 1) & 3;
  int lane = (idx >> 3) & 31;
  int t    = (idx >> 8) & 7;
  int h    = (idx >> 11) & 1;
  int step = idx >> 12;
  int b  = step % 3;
  int tc = step / 3;
  int ch = tc & 3, tap = tc >> 2;
  int o = t * 16 + (lane >> 2) + 8 * (r & 1);
  int k = 2 * (lane & 3) + 8 * (r >> 1) + e;
  int c = ch * 32 + h * 16 + k;
  const float* w = (b == 0) ? w0 : ((b == 1) ? w1 : w2);
  g_Wh[idx] = __float2half_rn(w[(o * CI + c) * 9 + tap]);
}

__device__ __forceinline__ void mma16816(float* c, const uint32_t* a,
                                         const uint32_t* b) {
  asm volatile(
      "mma.sync.aligned.m16n8k16.row.col.f32.f16.f16.f32 "
      "{%0,%1,%2,%3}, {%4,%5,%6,%7}, {%8,%9}, {%0,%1,%2,%3};"
      : "+f"(c[0]), "+f"(c[1]), "+f"(c[2]), "+f"(c[3])
      : "r"(a[0]), "r"(a[1]), "r"(a[2]), "r"(a[3]), "r"(b[0]), "r"(b[1]));
}
__device__ __forceinline__ uint32_t hmul2u(uint32_t a, uint32_t b) {
  __half2 r = __hmul2(*(__half2*)&a, *(__half2*)&b);
  return *(uint32_t*)&r;
}

__global__ __launch_bounds__(NTHR, 2) void conv25d_mma(
    const float* __restrict__ x, const float* __restrict__ depth,
    const float* __restrict__ fx, float* __restrict__ out) {
  __shared__ uint32_t Msm[27 * LT];   // half2(m,m)

  const int tid = threadIdx.x;
  const int n   = blockIdx.y;
  const int l0  = blockIdx.x * LT;
  const int h0  = l0 >> 6;
  const float* xn = x + (size_t)n * CI * HW;
  const float* dn = depth + (size_t)n * HW;

  // ---- mask precompute (verified math), packed half2 ----
  if (tid < LT) {
    int l = tid, h = h0 + (l >> 6), w = l & 63;
    float d[9];
#pragma unroll
    for (int kh = 0; kh < 3; ++kh)
#pragma unroll
      for (int kw = 0; kw < 3; ++kw) {
        int hh2 = h + kh - 1, ww2 = w + kw - 1;
        bool ok = (((unsigned)hh2) < HH) && (((unsigned)ww2) < WW);
        d[kh * 3 + kw] = ok ? dn[hh2 * WW + ww2] : 0.f;
      }
    float fxn = fx[n];
    float cvalid = (d[4] != 0.f) ? 1.f : 0.f;
    float center = d[4] * cvalid;
    float grid = center / fxn;
    float half = 0.5f * grid;
#pragma unroll
    for (int k = 0; k < 9; ++k) {
      float vld = (d[k] != 0.f) ? cvalid : 0.f;
      float dm = d[k] * vld;
      float m0 = (fabsf(dm - (center + grid)) <= half) ? 1.f : 0.f;
      float m1 = (fabsf(dm - center) <= half) ? 1.f : 0.f;
      m1 = fminf(m1 + 1.f - vld, 1.f);
      float m2 = (fabsf(dm - (center - grid)) <= half) ? 1.f : 0.f;
      __half2 p0 = __float2half2_rn(m0), p1 = __float2half2_rn(m1),
              p2 = __float2half2_rn(m2);
      Msm[(k * 3 + 0) * LT + l] = *(uint32_t*)&p0;
      Msm[(k * 3 + 1) * LT + l] = *(uint32_t*)&p1;
      Msm[(k * 3 + 2) * LT + l] = *(uint32_t*)&p2;
    }
  }
  __syncthreads();   // only barrier in the kernel

  const int lane = tid & 31;
  const int wq = tid >> 5;
  const int oq = wq >> 2, lq = wq & 3;      // warp tile: 64o x 32l
  const int g = lane >> 2, tig = lane & 3;
  const int lrow = lq >> 1;                 // image row within tile
  const int lcb  = (lq & 1) * 32;           // column base within row

  float acc[4][4][4];
#pragma unroll
  for (int i = 0; i < 4; ++i)
#pragma unroll
    for (int j = 0; j < 4; ++j)
#pragma unroll
      for (int r = 0; r < 4; ++r) acc[i][j][r] = 0.f;

  // B operand in registers: xv[p*4+j], p -> channel pair (c0, c0+1)
  uint32_t xv[16];

  const uint4* wfrag = (const uint4*)g_Wh;

#pragma unroll 1
  for (int tc = 0; tc < NTC; ++tc) {
    int tap = tc >> 2, ch = tc & 3;
    int dy = tap / 3 - 1, dx = tap % 3 - 1;
    int hrow = h0 + lrow + dy;
    bool okh = ((unsigned)hrow) < HH;
    const float* rb = xn + hrow * WW;

    // ---- load x fragment (32 scalar LDG, sector-friendly) ----
#pragma unroll
    for (int p = 0; p < 4; ++p) {
      int c0 = ch * 32 + (p >> 1) * 16 + (p & 1) * 8 + 2 * tig;
      const float* xp = rb + (size_t)c0 * HW;
#pragma unroll
      for (int j = 0; j < 4; ++j) {
        int w = lcb + j * 8 + g + dx;
        bool ok = okh && (((unsigned)w) < WW);
        float f0 = ok ? __ldg(xp + w) : 0.f;
        float f1 = ok ? __ldg(xp + HW + w) : 0.f;
        __half2 pk = __floats2half2_rn(f0, f1);
        xv[p * 4 + j] = *(uint32_t*)&pk;
      }
    }

    // ---- 3 branches reuse xv ----
#pragma unroll
    for (int b = 0; b < 3; ++b) {
      int it = tc * 3 + b;
      int s = tap * 3 + b;
      uint32_t msk[4];
#pragma unroll
      for (int j = 0; j < 4; ++j)
        msk[j] = Msm[s * LT + lq * 32 + j * 8 + g];

#pragma unroll
      for (int h = 0; h < 2; ++h) {
        uint32_t a[4][4];
#pragma unroll
        for (int i = 0; i < 4; ++i) {
          uint4 q = __ldg(&wfrag[(size_t)it * 512 + (h * 8 + oq * 4 + i) * 32 + lane]);
          a[i][0] = q.x; a[i][1] = q.y; a[i][2] = q.z; a[i][3] = q.w;
        }
#pragma unroll
        for (int j = 0; j < 4; ++j) {
          uint32_t bb[2];
          bb[0] = hmul2u(xv[(h * 2 + 0) * 4 + j], msk[j]);
          bb[1] = hmul2u(xv[(h * 2 + 1) * 4 + j], msk[j]);
#pragma unroll
          for (int i = 0; i < 4; ++i) mma16816(acc[i][j], a[i], bb);
        }
      }

      // warm next chunk's x lines into L1 during the middle branch
      if (b == 1 && tc + 1 < NTC) {
        int tcn = tc + 1, chn = tcn & 3, tapn = tcn >> 2;
        int dyn_ = tapn / 3 - 1;
        int hr = h0 + lrow + dyn_;
        if (((unsigned)hr) < HH) {
          const float* pa = xn + (size_t)(chn * 32 + lane) * HW + hr * WW + lcb;
          asm volatile("prefetch.global.L1 [%0];" ::"l"(pa));
        }
      }
    }
  }

  // ---- epilogue (round-4 verified mapping) ----
  float* on = out + (size_t)n * CO * HW;
#pragma unroll
  for (int i = 0; i < 4; ++i) {
    int obase = oq * 64 + i * 16 + g;
#pragma unroll
    for (int j = 0; j < 4; ++j) {
      int lcol = l0 + lq * 32 + j * 8 + 2 * tig;
      float2 v0 = make_float2(acc[i][j][0], acc[i][j][1]);
      float2 v1 = make_float2(acc[i][j][2], acc[i][j][3]);
      *(float2*)&on[(size_t)obase * HW + lcol] = v0;
      *(float2*)&on[(size_t)(obase + 8) * HW + lcol] = v1;
    }
  }
}

extern "C" void kernel_launch(void* const* d_in, const int* in_sizes, int n_in,
                              void* d_out, int out_size) {
  const float* x     = (const float*)d_in[0];
  const float* depth = (const float*)d_in[1];
  const float* fx    = (const float*)d_in[2];
  const float* w0    = (const float*)d_in[3];
  const float* w1    = (const float*)d_in[4];
  const float* w2    = (const float*)d_in[5];
  float* out = (float*)d_out;

  repack_kernel<<<(NIT * 4096 + 255) / 256, 256>>>(w0, w1, w2);
  dim3 grid((HH * WW) / LT, NB);
  conv25d_mma<<<grid, NTHR>>>(x, depth, fx, out);
}

// round 9
// speedup vs baseline: 1.3560x; 1.0571x over previous
#include <cuda_runtime.h>
#include <cuda_fp16.h>
#include <cstdint>
#include <math.h>

#define NB 8
#define CI 128
#define CO 128
#define HH 64
#define WW 64
#define HW (HH * WW)
#define LT 128
#define NIT 108            // 9 taps * 4 chunks(32ch) * 3 branches
#define NTC 36             // 9 taps * 4 chunks
#define NTHR 256

// Fragment-ready fp16 weights: [it(108)][khalf(2)][t(8)][lane(32)][r(4)][e(2)]
__device__ __align__(16) __half g_Wh[NIT * 4096];
// Pre-packed x: half2(x[2c2], x[2c2+1]) laid out [n][c2(64)][hw]
__device__ __align__(16) uint32_t g_Xh[NB * 64 * HW];

__global__ void repack_kernel(const float* __restrict__ w0,
                              const float* __restrict__ w1,
                              const float* __restrict__ w2) {
  int idx = blockIdx.x * blockDim.x + threadIdx.x;
  if (idx >= NIT * 4096) return;
  int e    = idx & 1;
  int r    = (idx >> 1) & 3;
  int lane = (idx >> 3) & 31;
  int t    = (idx >> 8) & 7;
  int h    = (idx >> 11) & 1;
  int step = idx >> 12;
  int b  = step % 3;
  int tc = step / 3;
  int ch = tc & 3, tap = tc >> 2;
  int o = t * 16 + (lane >> 2) + 8 * (r & 1);
  int k = 2 * (lane & 3) + 8 * (r >> 1) + e;
  int c = ch * 32 + h * 16 + k;
  const float* w = (b == 0) ? w0 : ((b == 1) ? w1 : w2);
  g_Wh[idx] = __float2half_rn(w[(o * CI + c) * 9 + tap]);
}

__global__ void prepack_x_kernel(const float* __restrict__ x) {
  int idx = blockIdx.x * blockDim.x + threadIdx.x;
  if (idx >= NB * 64 * HW) return;
  int hw = idx & (HW - 1);
  int c2 = (idx >> 12) & 63;
  int n  = idx >> 18;
  const float* xp = x + ((size_t)n * CI + 2 * c2) * HW + hw;
  __half2 p = __floats2half2_rn(xp[0], xp[HW]);
  g_Xh[idx] = *(uint32_t*)&p;
}

__device__ __forceinline__ void mma16816(float* c, const uint32_t* a,
                                         const uint32_t* b) {
  asm volatile(
      "mma.sync.aligned.m16n8k16.row.col.f32.f16.f16.f32 "
      "{%0,%1,%2,%3}, {%4,%5,%6,%7}, {%8,%9}, {%0,%1,%2,%3};"
      : "+f"(c[0]), "+f"(c[1]), "+f"(c[2]), "+f"(c[3])
      : "r"(a[0]), "r"(a[1]), "r"(a[2]), "r"(a[3]), "r"(b[0]), "r"(b[1]));
}
__device__ __forceinline__ uint32_t hmul2u(uint32_t a, uint32_t b) {
  __half2 r = __hmul2(*(__half2*)&a, *(__half2*)&b);
  return *(uint32_t*)&r;
}

__global__ __launch_bounds__(NTHR, 2) void conv25d_mma(
    const float* __restrict__ depth, const float* __restrict__ fx,
    float* __restrict__ out) {
  __shared__ uint32_t Msm[27 * LT];   // half2(m,m)

  const int tid = threadIdx.x;
  const int n   = blockIdx.y;
  const int l0  = blockIdx.x * LT;
  const int h0  = l0 >> 6;
  const uint32_t* xhn = g_Xh + (size_t)n * 64 * HW;
  const float* dn = depth + (size_t)n * HW;

  // ---- mask precompute (verified math), packed half2 ----
  if (tid < LT) {
    int l = tid, h = h0 + (l >> 6), w = l & 63;
    float d[9];
#pragma unroll
    for (int kh = 0; kh < 3; ++kh)
#pragma unroll
      for (int kw = 0; kw < 3; ++kw) {
        int hh2 = h + kh - 1, ww2 = w + kw - 1;
        bool ok = (((unsigned)hh2) < HH) && (((unsigned)ww2) < WW);
        d[kh * 3 + kw] = ok ? dn[hh2 * WW + ww2] : 0.f;
      }
    float fxn = fx[n];
    float cvalid = (d[4] != 0.f) ? 1.f : 0.f;
    float center = d[4] * cvalid;
    float grid = center / fxn;
    float half = 0.5f * grid;
#pragma unroll
    for (int k = 0; k < 9; ++k) {
      float vld = (d[k] != 0.f) ? cvalid : 0.f;
      float dm = d[k] * vld;
      float m0 = (fabsf(dm - (center + grid)) <= half) ? 1.f : 0.f;
      float m1 = (fabsf(dm - center) <= half) ? 1.f : 0.f;
      m1 = fminf(m1 + 1.f - vld, 1.f);
      float m2 = (fabsf(dm - (center - grid)) <= half) ? 1.f : 0.f;
      __half2 p0 = __float2half2_rn(m0), p1 = __float2half2_rn(m1),
              p2 = __float2half2_rn(m2);
      Msm[(k * 3 + 0) * LT + l] = *(uint32_t*)&p0;
      Msm[(k * 3 + 1) * LT + l] = *(uint32_t*)&p1;
      Msm[(k * 3 + 2) * LT + l] = *(uint32_t*)&p2;
    }
  }
  __syncthreads();   // only barrier in the kernel

  const int lane = tid & 31;
  const int wq = tid >> 5;
  const int oq = wq >> 2, lq = wq & 3;      // warp tile: 64o x 32l
  const int g = lane >> 2, tig = lane & 3;
  const int lrow = lq >> 1;
  const int lcb  = (lq & 1) * 32;

  float acc[4][4][4];
#pragma unroll
  for (int i = 0; i < 4; ++i)
#pragma unroll
    for (int j = 0; j < 4; ++j)
#pragma unroll
      for (int r = 0; r < 4; ++r) acc[i][j][r] = 0.f;

  uint32_t xv[16];   // packed half2 channel pairs, fragment-ready
  const uint4* wfrag = (const uint4*)g_Wh;

#pragma unroll 1
  for (int tc = 0; tc < NTC; ++tc) {
    int tap = tc >> 2, ch = tc & 3;
    int dy = tap / 3 - 1, dx = tap % 3 - 1;
    int hrow = h0 + lrow + dy;
    bool okh = ((unsigned)hrow) < HH;
    const uint32_t* rb = xhn + hrow * WW;

    // ---- load x fragment: 16 LDG.32 of pre-packed half2 ----
#pragma unroll
    for (int p = 0; p < 4; ++p) {
      int c2 = ch * 16 + (p >> 1) * 8 + (p & 1) * 4 + tig;
      const uint32_t* xp = rb + (size_t)c2 * HW;
#pragma unroll
      for (int j = 0; j < 4; ++j) {
        int w = lcb + j * 8 + g + dx;
        bool ok = okh && (((unsigned)w) < WW);
        xv[p * 4 + j] = ok ? __ldg(xp + w) : 0u;
      }
    }

    // ---- 3 branches reuse xv ----
#pragma unroll
    for (int b = 0; b < 3; ++b) {
      int it = tc * 3 + b;
      int s = tap * 3 + b;
      uint32_t msk[4];
#pragma unroll
      for (int j = 0; j < 4; ++j)
        msk[j] = Msm[s * LT + lq * 32 + j * 8 + g];

#pragma unroll
      for (int h = 0; h < 2; ++h) {
        uint32_t a[4][4];
#pragma unroll
        for (int i = 0; i < 4; ++i) {
          uint4 q = __ldg(&wfrag[(size_t)it * 512 + (h * 8 + oq * 4 + i) * 32 + lane]);
          a[i][0] = q.x; a[i][1] = q.y; a[i][2] = q.z; a[i][3] = q.w;
        }
#pragma unroll
        for (int j = 0; j < 4; ++j) {
          uint32_t bb[2];
          bb[0] = hmul2u(xv[(h * 2 + 0) * 4 + j], msk[j]);
          bb[1] = hmul2u(xv[(h * 2 + 1) * 4 + j], msk[j]);
#pragma unroll
          for (int i = 0; i < 4; ++i) mma16816(acc[i][j], a[i], bb);
        }
      }

      // one predicated prefetch covers the next chunk's full x footprint
      if (b == 1 && tc + 1 < NTC) {
        int tcn = tc + 1, chn = tcn & 3, tapn = tcn >> 2;
        int dyn_ = tapn / 3 - 1;
        int hr = h0 + lrow + dyn_;
        if (((unsigned)hr) < HH && lane < 16) {
          const uint32_t* pa = xhn + (size_t)(chn * 16 + lane) * HW + hr * WW + lcb;
          asm volatile("prefetch.global.L1 [%0];" ::"l"(pa));
        }
      }
    }
  }

  // ---- epilogue (verified mapping) ----
  float* on = out + (size_t)n * CO * HW;
#pragma unroll
  for (int i = 0; i < 4; ++i) {
    int obase = oq * 64 + i * 16 + g;
#pragma unroll
    for (int j = 0; j < 4; ++j) {
      int lcol = l0 + lq * 32 + j * 8 + 2 * tig;
      float2 v0 = make_float2(acc[i][j][0], acc[i][j][1]);
      float2 v1 = make_float2(acc[i][j][2], acc[i][j][3]);
      *(float2*)&on[(size_t)obase * HW + lcol] = v0;
      *(float2*)&on[(size_t)(obase + 8) * HW + lcol] = v1;
    }
  }
}

extern "C" void kernel_launch(void* const* d_in, const int* in_sizes, int n_in,
                              void* d_out, int out_size) {
  const float* x     = (const float*)d_in[0];
  const float* depth = (const float*)d_in[1];
  const float* fx    = (const float*)d_in[2];
  const float* w0    = (const float*)d_in[3];
  const float* w1    = (const float*)d_in[4];
  const float* w2    = (const float*)d_in[5];
  float* out = (float*)d_out;

  repack_kernel<<<(NIT * 4096 + 255) / 256, 256>>>(w0, w1, w2);
  prepack_x_kernel<<<(NB * 64 * HW + 255) / 256, 256>>>(x);
  dim3 grid((HH * WW) / LT, NB);
  conv25d_mma<<<grid, NTHR>>>(depth, fx, out);
}